// round 2
// baseline (speedup 1.0000x reference)
#include <cuda_runtime.h>

#define N_NODES 100000
#define N_EDGES 625000
#define D_IN    128
#define D_HID   256
#define NB      8          // nodes per block in the fused node kernel

// Scratch (allocation-free rule: __device__ globals)
__device__ float g_agg[(size_t)N_NODES * D_IN];
__device__ float g_cnt[N_NODES];

// ---------------------------------------------------------------------------
// Kernel 0: zero the scratch accumulators (must re-zero every replay)
// ---------------------------------------------------------------------------
__global__ void zero_kernel() {
    int i = blockIdx.x * blockDim.x + threadIdx.x;
    int stride = gridDim.x * blockDim.x;
    const int total4 = N_NODES * D_IN / 4;
    float4 z = make_float4(0.f, 0.f, 0.f, 0.f);
    for (int j = i; j < total4; j += stride)
        ((float4*)g_agg)[j] = z;
    for (int j = i; j < N_NODES; j += stride)
        g_cnt[j] = 0.f;
}

// ---------------------------------------------------------------------------
// Kernel 1: scatter-add over edges. One warp per edge; each lane handles a
// float4 (128 floats / 32 lanes). Vector reduction red.global.add.v4.f32
// (sm_90+) keeps the atomic op count at 20M instead of 80M.
// Edge indices arrive as int32 (harness downcasts the reference's int64).
// ---------------------------------------------------------------------------
__global__ void edge_kernel(const float* __restrict__ x,
                            const int* __restrict__ ei) {
    int w = blockIdx.x * (blockDim.x >> 5) + (threadIdx.x >> 5);
    if (w >= N_EDGES) return;
    int lane = threadIdx.x & 31;

    int src = ei[w];
    int dst = ei[N_EDGES + w];

    float4 v = ((const float4*)(x + (long long)src * D_IN))[lane];
    float* p = g_agg + (long long)dst * D_IN + lane * 4;
    asm volatile("red.global.add.v4.f32 [%0], {%1,%2,%3,%4};"
                 :: "l"(p), "f"(v.x), "f"(v.y), "f"(v.z), "f"(v.w)
                 : "memory");
    if (lane == 0)
        atomicAdd(&g_cnt[dst], 1.0f);
}

// ---------------------------------------------------------------------------
// Kernel 2: fused per-node pipeline.
//   mean = agg / max(cnt,1)
//   h = relu(mean @ w_l + b_l + x @ w_r)          [256]
//   pr = log_softmax(h @ w_p + b_p)               [7]
//   sv = log_softmax(h @ w_s + b_s)               [6]
// 64 threads/block, NB=8 nodes/block. Thread t owns output columns
// [4t, 4t+4) for all 8 nodes; weights loaded as float4 (LDG.128, L2-resident).
// ---------------------------------------------------------------------------
__global__ __launch_bounds__(64) void node_kernel(
    const float* __restrict__ x,
    const float* __restrict__ wl, const float* __restrict__ bl,
    const float* __restrict__ wr,
    const float* __restrict__ wp, const float* __restrict__ bp,
    const float* __restrict__ ws, const float* __restrict__ bs,
    float* __restrict__ out)
{
    __shared__ float s_x[NB][D_IN];
    __shared__ float s_m[NB][D_IN];
    __shared__ float s_h[NB][D_HID + 4];   // +4 pad: avoids 8-way LDS conflicts in epilogue
    __shared__ float s_o[NB][16];
    __shared__ float s_inv[NB];

    const int t = threadIdx.x;                 // 0..63
    const long long base = (long long)blockIdx.x * NB;

    if (t < NB) {
        float c = g_cnt[base + t];
        s_inv[t] = 1.0f / fmaxf(c, 1.0f);
    }
    __syncthreads();

    // Stage x and mean(=agg*inv) into shared
    for (int i = t; i < NB * (D_IN / 4); i += 64) {
        int n  = i >> 5;       // D_IN/4 == 32 float4 per node
        int kk = i & 31;
        float4 xv = ((const float4*)(x + (base + n) * D_IN))[kk];
        ((float4*)s_x[n])[kk] = xv;
        float4 av = ((const float4*)(g_agg + (base + n) * D_IN))[kk];
        float inv = s_inv[n];
        av.x *= inv; av.y *= inv; av.z *= inv; av.w *= inv;
        ((float4*)s_m[n])[kk] = av;
    }
    __syncthreads();

    // Main fused GEMM: acc[n] (float4) = b_l + mean@w_l + x@w_r for cols [4t,4t+4)
    float4 blv = ((const float4*)bl)[t];
    float4 acc[NB];
#pragma unroll
    for (int n = 0; n < NB; n++) acc[n] = blv;

    const float4* wl4p = (const float4*)wl;
    const float4* wr4p = (const float4*)wr;
#pragma unroll 4
    for (int k = 0; k < D_IN; k++) {
        float4 wl4 = wl4p[k * (D_HID / 4) + t];
        float4 wr4 = wr4p[k * (D_HID / 4) + t];
#pragma unroll
        for (int n = 0; n < NB; n++) {
            float m  = s_m[n][k];
            float xv = s_x[n][k];
            acc[n].x = fmaf(m, wl4.x, fmaf(xv, wr4.x, acc[n].x));
            acc[n].y = fmaf(m, wl4.y, fmaf(xv, wr4.y, acc[n].y));
            acc[n].z = fmaf(m, wl4.z, fmaf(xv, wr4.z, acc[n].z));
            acc[n].w = fmaf(m, wl4.w, fmaf(xv, wr4.w, acc[n].w));
        }
    }

    // ReLU + stash h in shared
#pragma unroll
    for (int n = 0; n < NB; n++) {
        float4 h = acc[n];
        h.x = fmaxf(h.x, 0.f); h.y = fmaxf(h.y, 0.f);
        h.z = fmaxf(h.z, 0.f); h.w = fmaxf(h.w, 0.f);
        float* row = s_h[n];
        row[4 * t + 0] = h.x; row[4 * t + 1] = h.y;
        row[4 * t + 2] = h.z; row[4 * t + 3] = h.w;
    }
    __syncthreads();

    // Small heads: 13 logits per node; 8 threads per node, each handles
    // columns slot, slot+8
    {
        int n    = t >> 3;
        int slot = t & 7;
        for (int c = slot; c < 13; c += 8) {
            float sum;
            if (c < 7) {
                sum = bp[c];
                const float* row = s_h[n];
#pragma unroll 8
                for (int j = 0; j < D_HID; j++)
                    sum = fmaf(row[j], wp[j * 7 + c], sum);
            } else {
                int cc = c - 7;
                sum = bs[cc];
                const float* row = s_h[n];
#pragma unroll 8
                for (int j = 0; j < D_HID; j++)
                    sum = fmaf(row[j], ws[j * 6 + cc], sum);
            }
            s_o[n][c] = sum;
        }
    }
    __syncthreads();

    // log_softmax + writeout: one thread per node
    if (t < NB) {
        int n = t;
        long long node = base + n;
        // pr: 7-way
        float mx = -1e30f;
#pragma unroll
        for (int c = 0; c < 7; c++) mx = fmaxf(mx, s_o[n][c]);
        float s = 0.f;
#pragma unroll
        for (int c = 0; c < 7; c++) s += __expf(s_o[n][c] - mx);
        float lse = mx + __logf(s);
#pragma unroll
        for (int c = 0; c < 7; c++) out[node * 7 + c] = s_o[n][c] - lse;
        // sv: 6-way
        mx = -1e30f;
#pragma unroll
        for (int c = 7; c < 13; c++) mx = fmaxf(mx, s_o[n][c]);
        s = 0.f;
#pragma unroll
        for (int c = 7; c < 13; c++) s += __expf(s_o[n][c] - mx);
        lse = mx + __logf(s);
        float* out2 = out + (long long)N_NODES * 7;
#pragma unroll
        for (int c = 0; c < 6; c++) out2[node * 6 + c] = s_o[n][7 + c] - lse;
    }
}

// ---------------------------------------------------------------------------
extern "C" void kernel_launch(void* const* d_in, const int* in_sizes, int n_in,
                              void* d_out, int out_size) {
    const float* x  = (const float*)d_in[0];
    const int*   ei = (const int*)d_in[1];
    const float* wl = (const float*)d_in[2];
    const float* bl = (const float*)d_in[3];
    const float* wr = (const float*)d_in[4];
    const float* wp = (const float*)d_in[5];
    const float* bp = (const float*)d_in[6];
    const float* ws = (const float*)d_in[7];
    const float* bs = (const float*)d_in[8];
    float* out = (float*)d_out;

    zero_kernel<<<512, 256>>>();

    // one warp per edge, 8 warps per block
    int edge_blocks = (N_EDGES + 7) / 8;
    edge_kernel<<<edge_blocks, 256>>>(x, ei);

    node_kernel<<<N_NODES / NB, 64>>>(x, wl, bl, wr, wp, bp, ws, bs, out);
}

// round 4
// speedup vs baseline: 1.1028x; 1.1028x over previous
#include <cuda_runtime.h>
#include <cstdint>

#define N_NODES 100000
#define N_EDGES 625000
#define D_IN    128
#define D_HID   256
#define NB      16         // nodes per block in the fused node kernel

typedef unsigned long long ull;

// ---------------------------------------------------------------------------
// Scratch (__device__ globals; allocation-free rule)
// ---------------------------------------------------------------------------
__device__ float g_agg[(size_t)N_NODES * D_IN];
__device__ float g_cnt[N_NODES];

// ---------------------------------------------------------------------------
// Packed f32x2 helpers (sm_100-family PTX; NOT an 'a'-only feature)
// ---------------------------------------------------------------------------
__device__ __forceinline__ ull fma2(ull a, ull b, ull c) {
    ull d;
    asm("fma.rn.f32x2 %0, %1, %2, %3;" : "=l"(d) : "l"(a), "l"(b), "l"(c));
    return d;
}
__device__ __forceinline__ ull pack2(float v) {
    ull d;
    asm("mov.b64 %0, {%1, %1};" : "=l"(d) : "r"(__float_as_uint(v)));
    return d;
}

// ---------------------------------------------------------------------------
// Kernel 0: zero the scratch accumulators (must re-zero every replay)
// ---------------------------------------------------------------------------
__global__ void zero_kernel() {
    int i = blockIdx.x * blockDim.x + threadIdx.x;
    int stride = gridDim.x * blockDim.x;
    const int total4 = N_NODES * D_IN / 4;
    float4 z = make_float4(0.f, 0.f, 0.f, 0.f);
    for (int j = i; j < total4; j += stride)
        ((float4*)g_agg)[j] = z;
    for (int j = i; j < N_NODES; j += stride)
        g_cnt[j] = 0.f;
}

// ---------------------------------------------------------------------------
// Kernel 1: edge scatter. One warp per edge, RED.128 vector reductions.
// ---------------------------------------------------------------------------
__global__ void edge_kernel(const float* __restrict__ x,
                            const int* __restrict__ ei) {
    int w = blockIdx.x * (blockDim.x >> 5) + (threadIdx.x >> 5);
    if (w >= N_EDGES) return;
    int lane = threadIdx.x & 31;

    int src = ei[w];
    int dst = ei[N_EDGES + w];

    float4 v = ((const float4*)(x + (long long)src * D_IN))[lane];
    float* p = g_agg + (long long)dst * D_IN + lane * 4;
    asm volatile("red.global.add.v4.f32 [%0], {%1,%2,%3,%4};"
                 :: "l"(p), "f"(v.x), "f"(v.y), "f"(v.z), "f"(v.w)
                 : "memory");
    if (lane == 0)
        atomicAdd(&g_cnt[dst], 1.0f);
}

// ---------------------------------------------------------------------------
// Kernel 2: fused per-node pipeline with packed f32x2 FMA.
//   h = relu(mean @ w_l + b_l + x @ w_r); heads; log_softmax.
// 64 threads/block, NB=16 nodes/block. Thread t owns cols [4t, 4t+4)
// as 2 packed f32x2 accumulators per node. Multipliers {m,m},{x,x} are
// pre-packed into shared b64 at staging so the inner loop is LDS.64+FFMA2.
// ---------------------------------------------------------------------------
__global__ __launch_bounds__(64) void node_kernel(
    const float* __restrict__ x,
    const float* __restrict__ wl, const float* __restrict__ bl,
    const float* __restrict__ wr,
    const float* __restrict__ wp, const float* __restrict__ bp,
    const float* __restrict__ ws, const float* __restrict__ bs,
    float* __restrict__ out)
{
    // s_pack[0] = {m,m} pairs, s_pack[1] = {x,x} pairs (32 KB total).
    // The whole region is reused as s_h (NB x 260 floats) after the main loop.
    __shared__ ull   s_pack[2][NB][D_IN];
    __shared__ float s_o[NB][16];
    __shared__ float s_inv[NB];

    const int t = threadIdx.x;                 // 0..63
    const long long base = (long long)blockIdx.x * NB;

    if (t < NB) {
        float c = g_cnt[base + t];
        s_inv[t] = 1.0f / fmaxf(c, 1.0f);
    }
    __syncthreads();

    // Stage packed multipliers into shared
    for (int i = t; i < NB * (D_IN / 4); i += 64) {   // 512 iters, 8/thread
        int n  = i >> 5;
        int kk = i & 31;
        float4 xv = ((const float4*)(x + (base + n) * D_IN))[kk];
        float4 av = ((const float4*)(g_agg + (base + n) * D_IN))[kk];
        float inv = s_inv[n];
        s_pack[1][n][kk * 4 + 0] = pack2(xv.x);
        s_pack[1][n][kk * 4 + 1] = pack2(xv.y);
        s_pack[1][n][kk * 4 + 2] = pack2(xv.z);
        s_pack[1][n][kk * 4 + 3] = pack2(xv.w);
        s_pack[0][n][kk * 4 + 0] = pack2(av.x * inv);
        s_pack[0][n][kk * 4 + 1] = pack2(av.y * inv);
        s_pack[0][n][kk * 4 + 2] = pack2(av.z * inv);
        s_pack[0][n][kk * 4 + 3] = pack2(av.w * inv);
    }
    __syncthreads();

    // Main fused GEMM, packed: acc0[n]={c0,c1}, acc1[n]={c2,c3} for cols 4t..
    ull acc0[NB], acc1[NB];
#pragma unroll
    for (int n = 0; n < NB; n++) { acc0[n] = 0ull; acc1[n] = 0ull; }

    const ulonglong2* wl2p = (const ulonglong2*)wl;   // row k = 64 x ull2
    const ulonglong2* wr2p = (const ulonglong2*)wr;
#pragma unroll 2
    for (int k = 0; k < D_IN; k++) {
        ulonglong2 wlv = wl2p[k * (D_HID / 4) + t];
        ulonglong2 wrv = wr2p[k * (D_HID / 4) + t];
#pragma unroll
        for (int n = 0; n < NB; n++) {
            ull m2 = s_pack[0][n][k];
            ull x2 = s_pack[1][n][k];
            acc0[n] = fma2(m2, wlv.x, fma2(x2, wrv.x, acc0[n]));
            acc1[n] = fma2(m2, wlv.y, fma2(x2, wrv.y, acc1[n]));
        }
    }
    __syncthreads();   // s_pack reads done; safe to overlay as s_h

    float* s_h = (float*)s_pack;               // [NB][260]
    const int HS = D_HID + 4;

    // Bias + ReLU + stash h
    float4 blv = ((const float4*)bl)[t];
#pragma unroll
    for (int n = 0; n < NB; n++) {
        float2 a0 = *(float2*)&acc0[n];
        float2 a1 = *(float2*)&acc1[n];
        float* row = s_h + n * HS;
        row[4 * t + 0] = fmaxf(a0.x + blv.x, 0.f);
        row[4 * t + 1] = fmaxf(a0.y + blv.y, 0.f);
        row[4 * t + 2] = fmaxf(a1.x + blv.z, 0.f);
        row[4 * t + 3] = fmaxf(a1.y + blv.w, 0.f);
    }
    __syncthreads();

    // Small heads: 13 logits/node; 4 threads per node
    {
        int n    = t >> 2;
        int slot = t & 3;
        const float* row = s_h + n * HS;
        for (int c = slot; c < 13; c += 4) {
            float sum;
            if (c < 7) {
                sum = bp[c];
#pragma unroll 8
                for (int j = 0; j < D_HID; j++)
                    sum = fmaf(row[j], wp[j * 7 + c], sum);
            } else {
                int cc = c - 7;
                sum = bs[cc];
#pragma unroll 8
                for (int j = 0; j < D_HID; j++)
                    sum = fmaf(row[j], ws[j * 6 + cc], sum);
            }
            s_o[n][c] = sum;
        }
    }
    __syncthreads();

    // log_softmax + writeout: one thread per node
    if (t < NB) {
        int n = t;
        long long node = base + n;
        float mx = -1e30f;
#pragma unroll
        for (int c = 0; c < 7; c++) mx = fmaxf(mx, s_o[n][c]);
        float s = 0.f;
#pragma unroll
        for (int c = 0; c < 7; c++) s += __expf(s_o[n][c] - mx);
        float lse = mx + __logf(s);
#pragma unroll
        for (int c = 0; c < 7; c++) out[node * 7 + c] = s_o[n][c] - lse;

        mx = -1e30f;
#pragma unroll
        for (int c = 7; c < 13; c++) mx = fmaxf(mx, s_o[n][c]);
        s = 0.f;
#pragma unroll
        for (int c = 7; c < 13; c++) s += __expf(s_o[n][c] - mx);
        lse = mx + __logf(s);
        float* out2 = out + (long long)N_NODES * 7;
#pragma unroll
        for (int c = 0; c < 6; c++) out2[node * 6 + c] = s_o[n][7 + c] - lse;
    }
}

// ---------------------------------------------------------------------------
extern "C" void kernel_launch(void* const* d_in, const int* in_sizes, int n_in,
                              void* d_out, int out_size) {
    const float* x  = (const float*)d_in[0];
    const int*   ei = (const int*)d_in[1];
    const float* wl = (const float*)d_in[2];
    const float* bl = (const float*)d_in[3];
    const float* wr = (const float*)d_in[4];
    const float* wp = (const float*)d_in[5];
    const float* bp = (const float*)d_in[6];
    const float* ws = (const float*)d_in[7];
    const float* bs = (const float*)d_in[8];
    float* out = (float*)d_out;

    zero_kernel<<<512, 256>>>();

    int edge_blocks = (N_EDGES + 7) / 8;   // one warp per edge
    edge_kernel<<<edge_blocks, 256>>>(x, ei);

    node_kernel<<<N_NODES / NB, 64>>>(x, wl, bl, wr, wp, bp, ws, bs, out);
}

// round 5
// speedup vs baseline: 1.6906x; 1.5329x over previous
#include <cuda_runtime.h>
#include <cuda_bf16.h>
#include <cstdint>

#define N_NODES 100000
#define N_EDGES 625000
#define D_IN    128
#define D_HID   256

// ---------------------------------------------------------------------------
// Scratch (__device__ globals; allocation-free rule)
// ---------------------------------------------------------------------------
__device__ float g_agg[(size_t)N_NODES * D_IN];
__device__ float g_cnt[N_NODES];
// Weight image W_cat^T: [img: hi/lo][n (256)][k (256)] bf16.
// k<128 -> w_l[k][n], k>=128 -> w_r[k-128][n].
__device__ __nv_bfloat16 g_Wt[2][256 * 256];

// ---------------------------------------------------------------------------
// Kernel 0: zero scratch
// ---------------------------------------------------------------------------
__global__ void zero_kernel() {
    int i = blockIdx.x * blockDim.x + threadIdx.x;
    int stride = gridDim.x * blockDim.x;
    const int total4 = N_NODES * D_IN / 4;
    float4 z = make_float4(0.f, 0.f, 0.f, 0.f);
    for (int j = i; j < total4; j += stride)
        ((float4*)g_agg)[j] = z;
    for (int j = i; j < N_NODES; j += stride)
        g_cnt[j] = 0.f;
}

// ---------------------------------------------------------------------------
// Kernel 1: edge scatter. One warp per edge, RED.128 vector reductions.
// ---------------------------------------------------------------------------
__global__ void edge_kernel(const float* __restrict__ x,
                            const int* __restrict__ ei) {
    int w = blockIdx.x * (blockDim.x >> 5) + (threadIdx.x >> 5);
    if (w >= N_EDGES) return;
    int lane = threadIdx.x & 31;

    int src = ei[w];
    int dst = ei[N_EDGES + w];

    float4 v = ((const float4*)(x + (long long)src * D_IN))[lane];
    float* p = g_agg + (long long)dst * D_IN + lane * 4;
    asm volatile("red.global.add.v4.f32 [%0], {%1,%2,%3,%4};"
                 :: "l"(p), "f"(v.x), "f"(v.y), "f"(v.z), "f"(v.w)
                 : "memory");
    if (lane == 0)
        atomicAdd(&g_cnt[dst], 1.0f);
}

// ---------------------------------------------------------------------------
// Kernel 2: build bf16 hi/lo weight image (W_cat^T, [n][k] layout)
// ---------------------------------------------------------------------------
__global__ void wconv_kernel(const float* __restrict__ wl,
                             const float* __restrict__ wr) {
    int idx = blockIdx.x * blockDim.x + threadIdx.x;   // 0..65535
    if (idx >= 256 * 256) return;
    int n = idx >> 8;
    int k = idx & 255;
    float v = (k < 128) ? wl[k * 256 + n] : wr[(k - 128) * 256 + n];
    __nv_bfloat16 hi = __float2bfloat16_rn(v);
    __nv_bfloat16 lo = __float2bfloat16_rn(v - __bfloat162float(hi));
    g_Wt[0][idx] = hi;
    g_Wt[1][idx] = lo;
}

// ---------------------------------------------------------------------------
// bf16 mma.sync helper (family-portable HMMA path, sm_80+)
// ---------------------------------------------------------------------------
__device__ __forceinline__ void mma_bf16(float* d, const uint32_t* a,
                                         uint32_t b0, uint32_t b1) {
    asm volatile(
        "mma.sync.aligned.m16n8k16.row.col.f32.bf16.bf16.f32 "
        "{%0,%1,%2,%3}, {%4,%5,%6,%7}, {%8,%9}, {%0,%1,%2,%3};"
        : "+f"(d[0]), "+f"(d[1]), "+f"(d[2]), "+f"(d[3])
        : "r"(a[0]), "r"(a[1]), "r"(a[2]), "r"(a[3]), "r"(b0), "r"(b1));
}

// ---------------------------------------------------------------------------
// Kernel 3: fused node kernel via bf16 hi/lo 3-pass mma.sync.
// Block = 512 threads (16 warps), M=128 nodes, N=256, K=256 in 4 chunks of 64.
// Warp tile: M32 x N64. D accumulated fp32 in regs (64/lane).
//
// SMEM (dynamic):
//   s_h   [128][260] f32 @ 0      (133120 B)  -- written after MMAs
//     overlay: s_A [2][128 rows][72 halfs] @ 0      (36864 B)
//              s_B [2][256 rows][72 halfs] @ 36864  (73728 B)
//   s_inv [128] f32      @ 133120
//   s_bl  [256] f32      @ 133632
//   s_wh  [16][260] f32  @ 134656 (transposed head weights; rows 13-15 pad)
//   s_bh  [16] f32       @ 151296
//   s_o   [128][16] f32  @ 151360
// ---------------------------------------------------------------------------
#define A_STRIDE 144          // bytes per A/B smem row (72 halfs)
#define AIMG     18432        // 128*144
#define SM_B_OFF 36864
#define BIMG     36864        // 256*144
#define H_STRIDE 260          // floats per h row
#define OFF_INV  133120
#define OFF_BL   133632
#define OFF_WH   134656
#define OFF_BH   151296
#define OFF_O    151360
#define SMEM_DYN (151360 + 128 * 16 * 4)   // 159552

__global__ __launch_bounds__(512, 1) void node_mma_kernel(
    const float* __restrict__ x,
    const float* __restrict__ wp, const float* __restrict__ bp,
    const float* __restrict__ ws, const float* __restrict__ bs,
    const float* __restrict__ bl,
    float* __restrict__ out)
{
    extern __shared__ char smem[];
    float* s_h   = (float*)smem;
    float* s_inv = (float*)(smem + OFF_INV);
    float* s_bl  = (float*)(smem + OFF_BL);
    float* s_wh  = (float*)(smem + OFF_WH);
    float* s_bh  = (float*)(smem + OFF_BH);
    float* s_o   = (float*)(smem + OFF_O);

    const int t    = threadIdx.x;
    const int w    = t >> 5;
    const int lane = t & 31;
    const int lq   = lane >> 2;        // 0..7
    const int lr   = (lane & 3) * 2;   // k half-offset
    const long long base = (long long)blockIdx.x * 128;

    // ---- stage small constants ----
    if (t < 128) {
        long long node = base + t;
        if (node >= N_NODES) node = N_NODES - 1;
        s_inv[t] = 1.0f / fmaxf(g_cnt[node], 1.0f);
    }
    if (t < 256) s_bl[t] = bl[t];
    for (int i = t; i < 13 * 256; i += 512) {
        int c = i >> 8, j = i & 255;
        s_wh[c * H_STRIDE + j] = (c < 7) ? wp[j * 7 + c] : ws[j * 6 + (c - 7)];
    }
    if (t < 16) s_bh[t] = (t < 7) ? bp[t] : (t < 13 ? bs[t - 7] : 0.f);

    // ---- MMA mainloop ----
    const int m0    = (w & 3) * 32;    // warp m-strip (M32)
    const int nbase = (w >> 2) * 64;   // warp n-strip (N64)

    float acc[64];                     // [mi(2)][nt(8)][4]
#pragma unroll
    for (int i = 0; i < 64; i++) acc[i] = 0.f;

    for (int c = 0; c < 4; c++) {
        __syncthreads();               // prior chunk's frag reads done

        // stage A chunk: 128 nodes x 64 k -> bf16 hi/lo
        for (int i = t; i < 2048; i += 512) {        // 2048 float4
            int m = i >> 4;
            int kl = (i & 15) * 4;
            long long node = base + m;
            if (node >= N_NODES) node = N_NODES - 1;
            const float* src = (c < 2)
                ? (g_agg + node * D_IN + c * 64 + kl)
                : (x + node * D_IN + (c - 2) * 64 + kl);
            float4 v = *(const float4*)src;
            if (c < 2) {
                float inv = s_inv[m];
                v.x *= inv; v.y *= inv; v.z *= inv; v.w *= inv;
            }
            __nv_bfloat16 h0 = __float2bfloat16_rn(v.x);
            __nv_bfloat16 h1 = __float2bfloat16_rn(v.y);
            __nv_bfloat16 h2 = __float2bfloat16_rn(v.z);
            __nv_bfloat16 h3 = __float2bfloat16_rn(v.w);
            __nv_bfloat16 l0 = __float2bfloat16_rn(v.x - __bfloat162float(h0));
            __nv_bfloat16 l1 = __float2bfloat16_rn(v.y - __bfloat162float(h1));
            __nv_bfloat16 l2 = __float2bfloat16_rn(v.z - __bfloat162float(h2));
            __nv_bfloat16 l3 = __float2bfloat16_rn(v.w - __bfloat162float(h3));
            uint2 hp, lp;
            hp.x = (uint32_t)__bfloat16_as_ushort(h0) | ((uint32_t)__bfloat16_as_ushort(h1) << 16);
            hp.y = (uint32_t)__bfloat16_as_ushort(h2) | ((uint32_t)__bfloat16_as_ushort(h3) << 16);
            lp.x = (uint32_t)__bfloat16_as_ushort(l0) | ((uint32_t)__bfloat16_as_ushort(l1) << 16);
            lp.y = (uint32_t)__bfloat16_as_ushort(l2) | ((uint32_t)__bfloat16_as_ushort(l3) << 16);
            char* p = smem + m * A_STRIDE + kl * 2;
            *(uint2*)p = hp;
            *(uint2*)(p + AIMG) = lp;
        }

        // stage B chunk: 256 n x 64 k, hi+lo, from g_Wt
        for (int img = 0; img < 2; img++) {
            const char* gsrc = (const char*)&g_Wt[img][0];
            for (int i = t; i < 2048; i += 512) {    // 2048 uint4
                int n = i >> 3;
                int q = i & 7;
                uint4 v = *(const uint4*)(gsrc + n * 512 + c * 128 + q * 16);
                *(uint4*)(smem + SM_B_OFF + img * BIMG + n * A_STRIDE + q * 16) = v;
            }
        }
        __syncthreads();

        // 3 passes: hi*hi, hi*lo, lo*hi
#pragma unroll
        for (int pass = 0; pass < 3; pass++) {
            const char* Ab = smem + ((pass == 2) ? AIMG : 0);
            const char* Bb = smem + SM_B_OFF + ((pass == 1) ? BIMG : 0);
#pragma unroll
            for (int ks = 0; ks < 4; ks++) {
                int kk = ks * 16 + lr;
                uint32_t a[2][4];
#pragma unroll
                for (int mi = 0; mi < 2; mi++) {
                    int r0 = m0 + mi * 16 + lq;
                    a[mi][0] = *(const uint32_t*)(Ab + r0 * A_STRIDE + kk * 2);
                    a[mi][1] = *(const uint32_t*)(Ab + (r0 + 8) * A_STRIDE + kk * 2);
                    a[mi][2] = *(const uint32_t*)(Ab + r0 * A_STRIDE + (kk + 8) * 2);
                    a[mi][3] = *(const uint32_t*)(Ab + (r0 + 8) * A_STRIDE + (kk + 8) * 2);
                }
#pragma unroll
                for (int nt = 0; nt < 8; nt++) {
                    int n = nbase + nt * 8 + lq;
                    uint32_t b0 = *(const uint32_t*)(Bb + n * A_STRIDE + kk * 2);
                    uint32_t b1 = *(const uint32_t*)(Bb + n * A_STRIDE + (kk + 8) * 2);
                    mma_bf16(acc + nt * 4, a[0], b0, b1);
                    mma_bf16(acc + 32 + nt * 4, a[1], b0, b1);
                }
            }
        }
    }
    __syncthreads();   // all frag reads done; safe to overlay s_h

    // ---- bias + relu, write h to smem ----
#pragma unroll
    for (int mi = 0; mi < 2; mi++) {
#pragma unroll
        for (int nt = 0; nt < 8; nt++) {
            const float* d = acc + mi * 32 + nt * 4;
            int col = nbase + nt * 8 + lr;
            int r0 = m0 + mi * 16 + lq;
            float b0 = s_bl[col], b1 = s_bl[col + 1];
            s_h[r0 * H_STRIDE + col]           = fmaxf(d[0] + b0, 0.f);
            s_h[r0 * H_STRIDE + col + 1]       = fmaxf(d[1] + b1, 0.f);
            s_h[(r0 + 8) * H_STRIDE + col]     = fmaxf(d[2] + b0, 0.f);
            s_h[(r0 + 8) * H_STRIDE + col + 1] = fmaxf(d[3] + b1, 0.f);
        }
    }
    __syncthreads();

    // ---- heads: 4 threads per node, thread covers c = slot + 4*ci ----
    {
        int m = t >> 2;
        int slot = t & 3;
        const float* hrow = s_h + m * H_STRIDE;
        float lacc[4] = {0.f, 0.f, 0.f, 0.f};
#pragma unroll 4
        for (int j4 = 0; j4 < 64; j4++) {
            float4 hv = *(const float4*)(hrow + j4 * 4);
#pragma unroll
            for (int ci = 0; ci < 4; ci++) {
                int cc = slot + ci * 4;          // 0..15 (13-15 read pad rows)
                float4 wv = *(const float4*)(s_wh + cc * H_STRIDE + j4 * 4);
                lacc[ci] += hv.x * wv.x + hv.y * wv.y + hv.z * wv.z + hv.w * wv.w;
            }
        }
#pragma unroll
        for (int ci = 0; ci < 4; ci++) {
            int cc = slot + ci * 4;
            if (cc < 13) s_o[m * 16 + cc] = lacc[ci] + s_bh[cc];
        }
    }
    __syncthreads();

    // ---- log_softmax + writeout ----
    if (t < 128) {
        long long node = base + t;
        if (node < N_NODES) {
            const float* o = s_o + t * 16;
            float mx = o[0];
#pragma unroll
            for (int cc = 1; cc < 7; cc++) mx = fmaxf(mx, o[cc]);
            float s = 0.f;
#pragma unroll
            for (int cc = 0; cc < 7; cc++) s += __expf(o[cc] - mx);
            float lse = mx + __logf(s);
#pragma unroll
            for (int cc = 0; cc < 7; cc++) out[node * 7 + cc] = o[cc] - lse;

            mx = o[7];
#pragma unroll
            for (int cc = 8; cc < 13; cc++) mx = fmaxf(mx, o[cc]);
            s = 0.f;
#pragma unroll
            for (int cc = 7; cc < 13; cc++) s += __expf(o[cc] - mx);
            lse = mx + __logf(s);
            float* out2 = out + (long long)N_NODES * 7;
#pragma unroll
            for (int cc = 0; cc < 6; cc++) out2[node * 6 + cc] = o[7 + cc] - lse;
        }
    }
}

// ---------------------------------------------------------------------------
extern "C" void kernel_launch(void* const* d_in, const int* in_sizes, int n_in,
                              void* d_out, int out_size) {
    const float* x  = (const float*)d_in[0];
    const int*   ei = (const int*)d_in[1];
    const float* wl = (const float*)d_in[2];
    const float* bl = (const float*)d_in[3];
    const float* wr = (const float*)d_in[4];
    const float* wp = (const float*)d_in[5];
    const float* bp = (const float*)d_in[6];
    const float* ws = (const float*)d_in[7];
    const float* bs = (const float*)d_in[8];
    float* out = (float*)d_out;

    cudaFuncSetAttribute(node_mma_kernel,
                         cudaFuncAttributeMaxDynamicSharedMemorySize, SMEM_DYN);

    zero_kernel<<<512, 256>>>();
    wconv_kernel<<<256, 256>>>(wl, wr);

    int edge_blocks = (N_EDGES + 7) / 8;   // one warp per edge
    edge_kernel<<<edge_blocks, 256>>>(x, ei);

    int node_blocks = (N_NODES + 127) / 128;   // 782
    node_mma_kernel<<<node_blocks, 512, SMEM_DYN>>>(x, wp, bp, ws, bs, bl, out);
}

// round 6
// speedup vs baseline: 1.7773x; 1.0513x over previous
#include <cuda_runtime.h>
#include <cuda_bf16.h>
#include <cstdint>

#define N_NODES 100000
#define N_EDGES 625000
#define D_IN    128
#define D_HID   256

// ---------------------------------------------------------------------------
// Scratch (__device__ globals; allocation-free rule)
// ---------------------------------------------------------------------------
__device__ float g_agg[(size_t)N_NODES * D_IN];
__device__ float g_cnt[N_NODES];
// Weight image W_cat^T: [img: hi/lo][n (256)][k (256)] bf16.
// k<128 -> w_l[k][n], k>=128 -> w_r[k-128][n].
__device__ __nv_bfloat16 g_Wt[2][256 * 256];

// ---------------------------------------------------------------------------
// Kernel 0: zero scratch
// ---------------------------------------------------------------------------
__global__ void zero_kernel() {
    int i = blockIdx.x * blockDim.x + threadIdx.x;
    int stride = gridDim.x * blockDim.x;
    const int total4 = N_NODES * D_IN / 4;
    float4 z = make_float4(0.f, 0.f, 0.f, 0.f);
    for (int j = i; j < total4; j += stride)
        ((float4*)g_agg)[j] = z;
    for (int j = i; j < N_NODES; j += stride)
        g_cnt[j] = 0.f;
}

// ---------------------------------------------------------------------------
// Kernel 1: edge scatter. One warp per edge, RED.128 vector reductions.
// ---------------------------------------------------------------------------
__global__ void edge_kernel(const float* __restrict__ x,
                            const int* __restrict__ ei) {
    int w = blockIdx.x * (blockDim.x >> 5) + (threadIdx.x >> 5);
    if (w >= N_EDGES) return;
    int lane = threadIdx.x & 31;

    int src = ei[w];
    int dst = ei[N_EDGES + w];

    float4 v = ((const float4*)(x + (long long)src * D_IN))[lane];
    float* p = g_agg + (long long)dst * D_IN + lane * 4;
    asm volatile("red.global.add.v4.f32 [%0], {%1,%2,%3,%4};"
                 :: "l"(p), "f"(v.x), "f"(v.y), "f"(v.z), "f"(v.w)
                 : "memory");
    if (lane == 0)
        atomicAdd(&g_cnt[dst], 1.0f);
}

// ---------------------------------------------------------------------------
// Kernel 2: build bf16 hi/lo weight image (W_cat^T, [n][k] layout)
// ---------------------------------------------------------------------------
__global__ void wconv_kernel(const float* __restrict__ wl,
                             const float* __restrict__ wr) {
    int idx = blockIdx.x * blockDim.x + threadIdx.x;   // 0..65535
    if (idx >= 256 * 256) return;
    int n = idx >> 8;
    int k = idx & 255;
    float v = (k < 128) ? wl[k * 256 + n] : wr[(k - 128) * 256 + n];
    __nv_bfloat16 hi = __float2bfloat16_rn(v);
    __nv_bfloat16 lo = __float2bfloat16_rn(v - __bfloat162float(hi));
    g_Wt[0][idx] = hi;
    g_Wt[1][idx] = lo;
}

// ---------------------------------------------------------------------------
// PTX helpers (all family-portable: sm_75/80+)
// ---------------------------------------------------------------------------
__device__ __forceinline__ uint32_t smem_u32(const void* p) {
    uint32_t a;
    asm("{ .reg .u64 t; cvta.to.shared.u64 t, %1; cvt.u32.u64 %0, t; }"
        : "=r"(a) : "l"(p));
    return a;
}
__device__ __forceinline__ void mma_bf16(float* d, const uint32_t* a,
                                         uint32_t b0, uint32_t b1) {
    asm volatile(
        "mma.sync.aligned.m16n8k16.row.col.f32.bf16.bf16.f32 "
        "{%0,%1,%2,%3}, {%4,%5,%6,%7}, {%8,%9}, {%0,%1,%2,%3};"
        : "+f"(d[0]), "+f"(d[1]), "+f"(d[2]), "+f"(d[3])
        : "r"(a[0]), "r"(a[1]), "r"(a[2]), "r"(a[3]), "r"(b0), "r"(b1));
}
#define LDSM4(d0, d1, d2, d3, addr) \
    asm volatile("ldmatrix.sync.aligned.m8n8.x4.shared.b16 {%0,%1,%2,%3}, [%4];" \
        : "=r"(d0), "=r"(d1), "=r"(d2), "=r"(d3) : "r"(addr))
#define CPASYNC16(dst, src) \
    asm volatile("cp.async.ca.shared.global [%0], [%1], 16;" :: "r"(dst), "l"(src))
#define CPCOMMIT() asm volatile("cp.async.commit_group;" ::: "memory")
#define CPWAIT0()  asm volatile("cp.async.wait_group 0;" ::: "memory")

// ---------------------------------------------------------------------------
// Kernel 3: pipelined bf16 hi/lo 3-pass mma.sync node kernel.
// Block = 512 threads (16 warps), M=128 nodes, N=256, K=256 in 4 chunks of 64.
// Double-buffered smem; B via cp.async overlapped with MMA; ldmatrix frags.
//
// SMEM: A bufs [2][2 img][128 rows][72 halfs] @ 0       (73728 B)
//       B bufs [2][2 img][256 rows][72 halfs] @ 73728   (147456 B)
//       s_inv [128] f32                       @ 221184
//       epilogue overlays buffers: s_h, s_wh, s_bl, s_bh, s_o
// ---------------------------------------------------------------------------
#define AST     144           // bytes per smem row (72 halfs)
#define A_IMG   18432         // 128*144
#define A_BUF   36864         // 2 imgs
#define B_OFF   73728
#define B_IMG   36864         // 256*144
#define B_BUF   73728
#define OFF_INV 221184
#define SMEM_DYN 221696
// epilogue overlays
#define H_STRIDE 260
#define E_WH  133120
#define E_BL  149760
#define E_BH  150784
#define E_O   150848

__global__ __launch_bounds__(512, 1) void node_mma_kernel(
    const float* __restrict__ x,
    const float* __restrict__ wp, const float* __restrict__ bp,
    const float* __restrict__ ws, const float* __restrict__ bs,
    const float* __restrict__ bl,
    float* __restrict__ out)
{
    extern __shared__ float4 smem4[];
    char* smem = (char*)smem4;
    const uint32_t sb = smem_u32(smem);
    float* s_inv = (float*)(smem + OFF_INV);

    const int t    = threadIdx.x;
    const int w    = t >> 5;
    const int lane = t & 31;
    const int lq   = lane >> 2;
    const int lr   = (lane & 3) * 2;
    const long long base = (long long)blockIdx.x * 128;

    if (t < 128) {
        long long node = base + t;
        if (node >= N_NODES) node = N_NODES - 1;
        s_inv[t] = 1.0f / fmaxf(g_cnt[node], 1.0f);
    }
    __syncthreads();

    const int m0    = (w & 3) * 32;
    const int nbase = (w >> 2) * 64;

    float acc[64];
#pragma unroll
    for (int i = 0; i < 64; i++) acc[i] = 0.f;

    // ---- staging helpers ----
    auto stageB = [&](int c, int buf) {
#pragma unroll
        for (int img = 0; img < 2; img++) {
            const char* gs = (const char*)&g_Wt[img][0];
#pragma unroll
            for (int it = 0; it < 4; it++) {
                int i = t + it * 512;
                int n = i >> 3, q = i & 7;
                uint32_t dst = sb + B_OFF + buf * B_BUF + img * B_IMG + n * AST + q * 16;
                CPASYNC16(dst, gs + n * 512 + c * 128 + q * 16);
            }
        }
    };
    auto stageA = [&](int c, int buf) {
        float4 v[4];
        int mm[4], kk[4];
#pragma unroll
        for (int it = 0; it < 4; it++) {
            int i = t + it * 512;
            int m = i >> 4, kl = (i & 15) * 4;
            mm[it] = m; kk[it] = kl;
            long long node = base + m;
            if (node >= N_NODES) node = N_NODES - 1;
            const float* src = (c < 2)
                ? (g_agg + node * D_IN + c * 64 + kl)
                : (x + node * D_IN + (c - 2) * 64 + kl);
            v[it] = *(const float4*)src;
        }
#pragma unroll
        for (int it = 0; it < 4; it++) {
            float4 vv = v[it];
            if (c < 2) {
                float inv = s_inv[mm[it]];
                vv.x *= inv; vv.y *= inv; vv.z *= inv; vv.w *= inv;
            }
            __nv_bfloat16 h0 = __float2bfloat16_rn(vv.x);
            __nv_bfloat16 h1 = __float2bfloat16_rn(vv.y);
            __nv_bfloat16 h2 = __float2bfloat16_rn(vv.z);
            __nv_bfloat16 h3 = __float2bfloat16_rn(vv.w);
            __nv_bfloat16 l0 = __float2bfloat16_rn(vv.x - __bfloat162float(h0));
            __nv_bfloat16 l1 = __float2bfloat16_rn(vv.y - __bfloat162float(h1));
            __nv_bfloat16 l2 = __float2bfloat16_rn(vv.z - __bfloat162float(h2));
            __nv_bfloat16 l3 = __float2bfloat16_rn(vv.w - __bfloat162float(h3));
            uint2 hp, lp;
            hp.x = (uint32_t)__bfloat16_as_ushort(h0) | ((uint32_t)__bfloat16_as_ushort(h1) << 16);
            hp.y = (uint32_t)__bfloat16_as_ushort(h2) | ((uint32_t)__bfloat16_as_ushort(h3) << 16);
            lp.x = (uint32_t)__bfloat16_as_ushort(l0) | ((uint32_t)__bfloat16_as_ushort(l1) << 16);
            lp.y = (uint32_t)__bfloat16_as_ushort(l2) | ((uint32_t)__bfloat16_as_ushort(l3) << 16);
            char* p = smem + buf * A_BUF + mm[it] * AST + kk[it] * 2;
            *(uint2*)p = hp;
            *(uint2*)(p + A_IMG) = lp;
        }
    };

    // ---- prologue: chunk 0 into buffer 0 ----
    stageB(0, 0); CPCOMMIT();
    stageA(0, 0);
    CPWAIT0();
    __syncthreads();

    // ---- pipelined mainloop ----
    for (int c = 0; c < 4; c++) {
        int cur = c & 1, nxt = cur ^ 1;
        if (c < 3) {
            stageB(c + 1, nxt); CPCOMMIT();   // DMA overlaps MMAs below
            stageA(c + 1, nxt);
        }

        const uint32_t Abase = sb + cur * A_BUF;
        const uint32_t Bbase = sb + B_OFF + cur * B_BUF;
        const int tt  = lane >> 3;
        const int arow = ((tt & 1) * 8) + (lane & 7);
        const int acol2 = ((tt >> 1) * 8) * 2;   // byte offset of k-half
#pragma unroll
        for (int pass = 0; pass < 3; pass++) {
            uint32_t Ab = Abase + ((pass == 2) ? A_IMG : 0);
            uint32_t Bb = Bbase + ((pass == 1) ? B_IMG : 0);
#pragma unroll
            for (int ks = 0; ks < 4; ks++) {
                int kb = ks * 32;   // byte offset of k-chunk (16 halfs)
                uint32_t a0[4], a1[4];
                uint32_t ad = Ab + (m0 + arow) * AST + kb + acol2;
                LDSM4(a0[0], a0[1], a0[2], a0[3], ad);
                LDSM4(a1[0], a1[1], a1[2], a1[3], ad + 16 * AST);
#pragma unroll
                for (int j = 0; j < 4; j++) {
                    uint32_t b[4];
                    uint32_t bd = Bb + (nbase + j * 16 + arow) * AST + kb + acol2;
                    LDSM4(b[0], b[1], b[2], b[3], bd);
                    // b0: n+0..7 k-lo | b1: n+8..15 k-lo | b2: n+0..7 k-hi | b3: n+8..15 k-hi
                    int nt0 = j * 2, nt1 = j * 2 + 1;
                    mma_bf16(acc + nt0 * 4,      a0, b[0], b[2]);
                    mma_bf16(acc + nt1 * 4,      a0, b[1], b[3]);
                    mma_bf16(acc + 32 + nt0 * 4, a1, b[0], b[2]);
                    mma_bf16(acc + 32 + nt1 * 4, a1, b[1], b[3]);
                }
            }
        }
        if (c < 3) CPWAIT0();
        __syncthreads();
    }

    // ---- epilogue: overlay buffers ----
    float* s_h  = (float*)smem;
    float* s_wh = (float*)(smem + E_WH);
    float* s_bl = (float*)(smem + E_BL);
    float* s_bh = (float*)(smem + E_BH);
    float* s_o  = (float*)(smem + E_O);

    if (t < 256) s_bl[t] = bl[t];
    for (int i = t; i < 13 * 256; i += 512) {
        int cc = i >> 8, j = i & 255;
        s_wh[cc * H_STRIDE + j] = (cc < 7) ? wp[j * 7 + cc] : ws[j * 6 + (cc - 7)];
    }
    if (t < 16) s_bh[t] = (t < 7) ? bp[t] : (t < 13 ? bs[t - 7] : 0.f);
    __syncthreads();

    // bias + relu, write h
#pragma unroll
    for (int mi = 0; mi < 2; mi++) {
#pragma unroll
        for (int nt = 0; nt < 8; nt++) {
            const float* d = acc + mi * 32 + nt * 4;
            int col = nbase + nt * 8 + lr;
            int r0 = m0 + mi * 16 + lq;
            float b0 = s_bl[col], b1 = s_bl[col + 1];
            s_h[r0 * H_STRIDE + col]           = fmaxf(d[0] + b0, 0.f);
            s_h[r0 * H_STRIDE + col + 1]       = fmaxf(d[1] + b1, 0.f);
            s_h[(r0 + 8) * H_STRIDE + col]     = fmaxf(d[2] + b0, 0.f);
            s_h[(r0 + 8) * H_STRIDE + col + 1] = fmaxf(d[3] + b1, 0.f);
        }
    }
    __syncthreads();

    // heads: 4 threads per node
    {
        int m = t >> 2;
        int slot = t & 3;
        const float* hrow = s_h + m * H_STRIDE;
        float lacc[4] = {0.f, 0.f, 0.f, 0.f};
#pragma unroll 4
        for (int j4 = 0; j4 < 64; j4++) {
            float4 hv = *(const float4*)(hrow + j4 * 4);
#pragma unroll
            for (int ci = 0; ci < 4; ci++) {
                int cc = slot + ci * 4;
                float4 wv = *(const float4*)(s_wh + cc * H_STRIDE + j4 * 4);
                lacc[ci] += hv.x * wv.x + hv.y * wv.y + hv.z * wv.z + hv.w * wv.w;
            }
        }
#pragma unroll
        for (int ci = 0; ci < 4; ci++) {
            int cc = slot + ci * 4;
            if (cc < 13) s_o[m * 16 + cc] = lacc[ci] + s_bh[cc];
        }
    }
    __syncthreads();

    // log_softmax + writeout
    if (t < 128) {
        long long node = base + t;
        if (node < N_NODES) {
            const float* o = s_o + t * 16;
            float mx = o[0];
#pragma unroll
            for (int cc = 1; cc < 7; cc++) mx = fmaxf(mx, o[cc]);
            float s = 0.f;
#pragma unroll
            for (int cc = 0; cc < 7; cc++) s += __expf(o[cc] - mx);
            float lse = mx + __logf(s);
#pragma unroll
            for (int cc = 0; cc < 7; cc++) out[node * 7 + cc] = o[cc] - lse;

            mx = o[7];
#pragma unroll
            for (int cc = 8; cc < 13; cc++) mx = fmaxf(mx, o[cc]);
            s = 0.f;
#pragma unroll
            for (int cc = 7; cc < 13; cc++) s += __expf(o[cc] - mx);
            lse = mx + __logf(s);
            float* out2 = out + (long long)N_NODES * 7;
#pragma unroll
            for (int cc = 0; cc < 6; cc++) out2[node * 6 + cc] = o[7 + cc] - lse;
        }
    }
}

// ---------------------------------------------------------------------------
extern "C" void kernel_launch(void* const* d_in, const int* in_sizes, int n_in,
                              void* d_out, int out_size) {
    const float* x  = (const float*)d_in[0];
    const int*   ei = (const int*)d_in[1];
    const float* wl = (const float*)d_in[2];
    const float* bl = (const float*)d_in[3];
    const float* wr = (const float*)d_in[4];
    const float* wp = (const float*)d_in[5];
    const float* bp = (const float*)d_in[6];
    const float* ws = (const float*)d_in[7];
    const float* bs = (const float*)d_in[8];
    float* out = (float*)d_out;

    cudaFuncSetAttribute(node_mma_kernel,
                         cudaFuncAttributeMaxDynamicSharedMemorySize, SMEM_DYN);

    zero_kernel<<<512, 256>>>();
    wconv_kernel<<<256, 256>>>(wl, wr);

    int edge_blocks = (N_EDGES + 7) / 8;   // one warp per edge
    edge_kernel<<<edge_blocks, 256>>>(x, ei);

    int node_blocks = (N_NODES + 127) / 128;   // 782
    node_mma_kernel<<<node_blocks, 512, SMEM_DYN>>>(x, wp, bp, ws, bs, bl, out);
}

// round 7
// speedup vs baseline: 1.9630x; 1.1045x over previous
#include <cuda_runtime.h>
#include <cuda_bf16.h>
#include <cstdint>

#define N_NODES 100000
#define N_EDGES 625000
#define D_IN    128
#define D_HID   256

// ---------------------------------------------------------------------------
// Scratch (__device__ globals; allocation-free rule)
// ---------------------------------------------------------------------------
__device__ float g_agg[(size_t)N_NODES * D_IN];
__device__ float g_cnt[N_NODES];
// Weight image W_cat^T: [img: hi/lo][n (256)][k (256)] bf16.
__device__ __nv_bfloat16 g_Wt[2][256 * 256];

// ---------------------------------------------------------------------------
// Kernel 0: zero scratch
// ---------------------------------------------------------------------------
__global__ void zero_kernel() {
    int i = blockIdx.x * blockDim.x + threadIdx.x;
    int stride = gridDim.x * blockDim.x;
    const int total4 = N_NODES * D_IN / 4;
    float4 z = make_float4(0.f, 0.f, 0.f, 0.f);
    for (int j = i; j < total4; j += stride)
        ((float4*)g_agg)[j] = z;
    for (int j = i; j < N_NODES; j += stride)
        g_cnt[j] = 0.f;
}

// ---------------------------------------------------------------------------
// Kernel 1: edge scatter. One warp per edge, RED.128 vector reductions.
// ---------------------------------------------------------------------------
__global__ void edge_kernel(const float* __restrict__ x,
                            const int* __restrict__ ei) {
    int w = blockIdx.x * (blockDim.x >> 5) + (threadIdx.x >> 5);
    if (w >= N_EDGES) return;
    int lane = threadIdx.x & 31;

    int src = ei[w];
    int dst = ei[N_EDGES + w];

    float4 v = ((const float4*)(x + (long long)src * D_IN))[lane];
    float* p = g_agg + (long long)dst * D_IN + lane * 4;
    asm volatile("red.global.add.v4.f32 [%0], {%1,%2,%3,%4};"
                 :: "l"(p), "f"(v.x), "f"(v.y), "f"(v.z), "f"(v.w)
                 : "memory");
    if (lane == 0)
        atomicAdd(&g_cnt[dst], 1.0f);
}

// ---------------------------------------------------------------------------
// Kernel 2: build bf16 hi/lo weight image (W_cat^T, [n][k] layout)
// ---------------------------------------------------------------------------
__global__ void wconv_kernel(const float* __restrict__ wl,
                             const float* __restrict__ wr) {
    int idx = blockIdx.x * blockDim.x + threadIdx.x;
    if (idx >= 256 * 256) return;
    int n = idx >> 8;
    int k = idx & 255;
    float v = (k < 128) ? wl[k * 256 + n] : wr[(k - 128) * 256 + n];
    __nv_bfloat16 hi = __float2bfloat16_rn(v);
    __nv_bfloat16 lo = __float2bfloat16_rn(v - __bfloat162float(hi));
    g_Wt[0][idx] = hi;
    g_Wt[1][idx] = lo;
}

// ---------------------------------------------------------------------------
// PTX helpers (family-portable: sm_75/80+)
// ---------------------------------------------------------------------------
__device__ __forceinline__ uint32_t smem_u32(const void* p) {
    uint32_t a;
    asm("{ .reg .u64 t; cvta.to.shared.u64 t, %1; cvt.u32.u64 %0, t; }"
        : "=r"(a) : "l"(p));
    return a;
}
__device__ __forceinline__ void mma_bf16(float* d, const uint32_t* a,
                                         uint32_t b0, uint32_t b1) {
    asm volatile(
        "mma.sync.aligned.m16n8k16.row.col.f32.bf16.bf16.f32 "
        "{%0,%1,%2,%3}, {%4,%5,%6,%7}, {%8,%9}, {%0,%1,%2,%3};"
        : "+f"(d[0]), "+f"(d[1]), "+f"(d[2]), "+f"(d[3])
        : "r"(a[0]), "r"(a[1]), "r"(a[2]), "r"(a[3]), "r"(b0), "r"(b1));
}
#define LDSM4(d0, d1, d2, d3, addr) \
    asm volatile("ldmatrix.sync.aligned.m8n8.x4.shared.b16 {%0,%1,%2,%3}, [%4];" \
        : "=r"(d0), "=r"(d1), "=r"(d2), "=r"(d3) : "r"(addr))
#define CPASYNC16(dst, src) \
    asm volatile("cp.async.ca.shared.global [%0], [%1], 16;" :: "r"(dst), "l"(src))
#define CPCOMMIT() asm volatile("cp.async.commit_group;" ::: "memory")
#define CPWAIT0()  asm volatile("cp.async.wait_group 0;" ::: "memory")

// ---------------------------------------------------------------------------
// Kernel 3: bf16 hi/lo 3-pass mma.sync node kernel, 2 CTAs/SM.
// Block = 256 threads (8 warps), M=64 nodes, N=256, K=256 in 4 chunks of 64.
// A double-buffered (LDG+convert overlaps B DMA); B single-buffered cp.async.
//
// SMEM/CTA (110,848 B -> 2 CTAs/SM):
//   A bufs [2 buf][2 img][64 rows][72 halfs] @ 0       (36,864)
//   B buf  [2 img][256 rows][72 halfs]       @ 36,864  (73,728)
//   s_inv  [64] f32                          @ 110,592
//   epilogue overlays A/B region.
// ---------------------------------------------------------------------------
#define AST     144
#define A_IMG   9216          // 64*144
#define A_BUF   18432         // 2 imgs
#define B_OFF   36864
#define B_IMG   36864         // 256*144
#define OFF_INV 110592
#define SMEM_DYN 110848
// epilogue overlays
#define H_STRIDE 260
#define E_WH  66560           // s_h = 64*260*4 = 66,560 @ 0
#define E_BL  83200
#define E_BH  84224
#define E_O   84288           // + 64*16*4 = 88,384 total < 110,592

__global__ __launch_bounds__(256, 2) void node_mma_kernel(
    const float* __restrict__ x,
    const float* __restrict__ wp, const float* __restrict__ bp,
    const float* __restrict__ ws, const float* __restrict__ bs,
    const float* __restrict__ bl,
    float* __restrict__ out)
{
    extern __shared__ float4 smem4[];
    char* smem = (char*)smem4;
    const uint32_t sb = smem_u32(smem);
    float* s_inv = (float*)(smem + OFF_INV);

    const int t    = threadIdx.x;
    const int w    = t >> 5;
    const int lane = t & 31;
    const int lq   = lane >> 2;
    const int lr   = (lane & 3) * 2;
    const long long base = (long long)blockIdx.x * 64;

    if (t < 64) {
        long long node = base + t;
        if (node >= N_NODES) node = N_NODES - 1;
        s_inv[t] = 1.0f / fmaxf(g_cnt[node], 1.0f);
    }
    __syncthreads();

    const int m0    = (w & 1) * 32;    // 2 M-strips
    const int nbase = (w >> 1) * 64;   // 4 N-strips

    float acc[64];
#pragma unroll
    for (int i = 0; i < 64; i++) acc[i] = 0.f;

    // ---- staging helpers ----
    auto stageB = [&](int c) {         // 4096 cp.async.16 across 256 threads
#pragma unroll
        for (int img = 0; img < 2; img++) {
            const char* gs = (const char*)&g_Wt[img][0];
#pragma unroll
            for (int it = 0; it < 8; it++) {
                int i = t + it * 256;
                int n = i >> 3, q = i & 7;
                uint32_t dst = sb + B_OFF + img * B_IMG + n * AST + q * 16;
                CPASYNC16(dst, gs + n * 512 + c * 128 + q * 16);
            }
        }
    };
    auto stageA = [&](int c, int buf) {   // 64 rows x 64 k = 1024 float4
        float4 v[4];
        int mm[4], kk[4];
#pragma unroll
        for (int it = 0; it < 4; it++) {
            int i = t + it * 256;
            int m = i >> 4, kl = (i & 15) * 4;
            mm[it] = m; kk[it] = kl;
            long long node = base + m;
            if (node >= N_NODES) node = N_NODES - 1;
            const float* src = (c < 2)
                ? (g_agg + node * D_IN + c * 64 + kl)
                : (x + node * D_IN + (c - 2) * 64 + kl);
            v[it] = *(const float4*)src;
        }
#pragma unroll
        for (int it = 0; it < 4; it++) {
            float4 vv = v[it];
            if (c < 2) {
                float inv = s_inv[mm[it]];
                vv.x *= inv; vv.y *= inv; vv.z *= inv; vv.w *= inv;
            }
            __nv_bfloat16 h0 = __float2bfloat16_rn(vv.x);
            __nv_bfloat16 h1 = __float2bfloat16_rn(vv.y);
            __nv_bfloat16 h2 = __float2bfloat16_rn(vv.z);
            __nv_bfloat16 h3 = __float2bfloat16_rn(vv.w);
            __nv_bfloat16 l0 = __float2bfloat16_rn(vv.x - __bfloat162float(h0));
            __nv_bfloat16 l1 = __float2bfloat16_rn(vv.y - __bfloat162float(h1));
            __nv_bfloat16 l2 = __float2bfloat16_rn(vv.z - __bfloat162float(h2));
            __nv_bfloat16 l3 = __float2bfloat16_rn(vv.w - __bfloat162float(h3));
            uint2 hp, lp;
            hp.x = (uint32_t)__bfloat16_as_ushort(h0) | ((uint32_t)__bfloat16_as_ushort(h1) << 16);
            hp.y = (uint32_t)__bfloat16_as_ushort(h2) | ((uint32_t)__bfloat16_as_ushort(h3) << 16);
            lp.x = (uint32_t)__bfloat16_as_ushort(l0) | ((uint32_t)__bfloat16_as_ushort(l1) << 16);
            lp.y = (uint32_t)__bfloat16_as_ushort(l2) | ((uint32_t)__bfloat16_as_ushort(l3) << 16);
            char* p = smem + buf * A_BUF + mm[it] * AST + kk[it] * 2;
            *(uint2*)p = hp;
            *(uint2*)(p + A_IMG) = lp;
        }
    };

    // ---- prologue ----
    stageA(0, 0);

    // ---- mainloop: B single-buffered, A double-buffered ----
    for (int c = 0; c < 4; c++) {
        int cur = c & 1, nxt = cur ^ 1;
        __syncthreads();                  // prior MMAs done with B buf & A alt
        stageB(c); CPCOMMIT();            // DMA fill of B(c)
        if (c < 3) stageA(c + 1, nxt);    // overlaps B DMA
        CPWAIT0();
        __syncthreads();                  // B(c) + A(c) visible

        const uint32_t Abase = sb + cur * A_BUF;
        const uint32_t Bbase = sb + B_OFF;
        const int tt   = lane >> 3;
        const int arow = ((tt & 1) * 8) + (lane & 7);
        const int acol2 = ((tt >> 1) * 8) * 2;
#pragma unroll
        for (int pass = 0; pass < 3; pass++) {
            uint32_t Ab = Abase + ((pass == 2) ? A_IMG : 0);
            uint32_t Bb = Bbase + ((pass == 1) ? B_IMG : 0);
#pragma unroll
            for (int ks = 0; ks < 4; ks++) {
                int kb = ks * 32;
                uint32_t a0[4], a1[4], b[4][4];
                uint32_t ad = Ab + (m0 + arow) * AST + kb + acol2;
                // batch all fragment loads for MLP, then run 16 MMAs
                LDSM4(a0[0], a0[1], a0[2], a0[3], ad);
                LDSM4(a1[0], a1[1], a1[2], a1[3], ad + 16 * AST);
#pragma unroll
                for (int j = 0; j < 4; j++) {
                    uint32_t bd = Bb + (nbase + j * 16 + arow) * AST + kb + acol2;
                    LDSM4(b[j][0], b[j][1], b[j][2], b[j][3], bd);
                }
#pragma unroll
                for (int j = 0; j < 4; j++) {
                    int nt0 = j * 2, nt1 = j * 2 + 1;
                    mma_bf16(acc + nt0 * 4,      a0, b[j][0], b[j][2]);
                    mma_bf16(acc + nt1 * 4,      a0, b[j][1], b[j][3]);
                    mma_bf16(acc + 32 + nt0 * 4, a1, b[j][0], b[j][2]);
                    mma_bf16(acc + 32 + nt1 * 4, a1, b[j][1], b[j][3]);
                }
            }
        }
    }
    __syncthreads();

    // ---- epilogue: overlay buffers ----
    float* s_h  = (float*)smem;
    float* s_wh = (float*)(smem + E_WH);
    float* s_bl = (float*)(smem + E_BL);
    float* s_bh = (float*)(smem + E_BH);
    float* s_o  = (float*)(smem + E_O);

    if (t < 256) s_bl[t] = bl[t];
    for (int i = t; i < 13 * 256; i += 256) {
        int cc = i >> 8, j = i & 255;
        s_wh[cc * H_STRIDE + j] = (cc < 7) ? wp[j * 7 + cc] : ws[j * 6 + (cc - 7)];
    }
    if (t < 16) s_bh[t] = (t < 7) ? bp[t] : (t < 13 ? bs[t - 7] : 0.f);
    __syncthreads();

    // bias + relu, write h
#pragma unroll
    for (int mi = 0; mi < 2; mi++) {
#pragma unroll
        for (int nt = 0; nt < 8; nt++) {
            const float* d = acc + mi * 32 + nt * 4;
            int col = nbase + nt * 8 + lr;
            int r0 = m0 + mi * 16 + lq;
            float b0 = s_bl[col], b1 = s_bl[col + 1];
            s_h[r0 * H_STRIDE + col]           = fmaxf(d[0] + b0, 0.f);
            s_h[r0 * H_STRIDE + col + 1]       = fmaxf(d[1] + b1, 0.f);
            s_h[(r0 + 8) * H_STRIDE + col]     = fmaxf(d[2] + b0, 0.f);
            s_h[(r0 + 8) * H_STRIDE + col + 1] = fmaxf(d[3] + b1, 0.f);
        }
    }
    __syncthreads();

    // heads: 4 threads per node (256 thr / 4 = 64 nodes)
    {
        int m = t >> 2;
        int slot = t & 3;
        const float* hrow = s_h + m * H_STRIDE;
        float lacc[4] = {0.f, 0.f, 0.f, 0.f};
#pragma unroll 4
        for (int j4 = 0; j4 < 64; j4++) {
            float4 hv = *(const float4*)(hrow + j4 * 4);
#pragma unroll
            for (int ci = 0; ci < 4; ci++) {
                int cc = slot + ci * 4;
                float4 wv = *(const float4*)(s_wh + cc * H_STRIDE + j4 * 4);
                lacc[ci] += hv.x * wv.x + hv.y * wv.y + hv.z * wv.z + hv.w * wv.w;
            }
        }
#pragma unroll
        for (int ci = 0; ci < 4; ci++) {
            int cc = slot + ci * 4;
            if (cc < 13) s_o[m * 16 + cc] = lacc[ci] + s_bh[cc];
        }
    }
    __syncthreads();

    // log_softmax + writeout
    if (t < 64) {
        long long node = base + t;
        if (node < N_NODES) {
            const float* o = s_o + t * 16;
            float mx = o[0];
#pragma unroll
            for (int cc = 1; cc < 7; cc++) mx = fmaxf(mx, o[cc]);
            float s = 0.f;
#pragma unroll
            for (int cc = 0; cc < 7; cc++) s += __expf(o[cc] - mx);
            float lse = mx + __logf(s);
#pragma unroll
            for (int cc = 0; cc < 7; cc++) out[node * 7 + cc] = o[cc] - lse;

            mx = o[7];
#pragma unroll
            for (int cc = 8; cc < 13; cc++) mx = fmaxf(mx, o[cc]);
            s = 0.f;
#pragma unroll
            for (int cc = 7; cc < 13; cc++) s += __expf(o[cc] - mx);
            lse = mx + __logf(s);
            float* out2 = out + (long long)N_NODES * 7;
#pragma unroll
            for (int cc = 0; cc < 6; cc++) out2[node * 6 + cc] = o[7 + cc] - lse;
        }
    }
}

// ---------------------------------------------------------------------------
extern "C" void kernel_launch(void* const* d_in, const int* in_sizes, int n_in,
                              void* d_out, int out_size) {
    const float* x  = (const float*)d_in[0];
    const int*   ei = (const int*)d_in[1];
    const float* wl = (const float*)d_in[2];
    const float* bl = (const float*)d_in[3];
    const float* wr = (const float*)d_in[4];
    const float* wp = (const float*)d_in[5];
    const float* bp = (const float*)d_in[6];
    const float* ws = (const float*)d_in[7];
    const float* bs = (const float*)d_in[8];
    float* out = (float*)d_out;

    cudaFuncSetAttribute(node_mma_kernel,
                         cudaFuncAttributeMaxDynamicSharedMemorySize, SMEM_DYN);

    zero_kernel<<<512, 256>>>();
    wconv_kernel<<<256, 256>>>(wl, wr);

    int edge_blocks = (N_EDGES + 7) / 8;   // one warp per edge
    edge_kernel<<<edge_blocks, 256>>>(x, ei);

    int node_blocks = (N_NODES + 63) / 64;   // 1563
    node_mma_kernel<<<node_blocks, 256, SMEM_DYN>>>(x, wp, bp, ws, bs, bl, out);
}